// round 15
// baseline (speedup 1.0000x reference)
#include <cuda_runtime.h>

#define HID    32
#define EMB    32
#define BD     32
#define VOCABN 50257
#define S_SRC  64
#define NSTEP  63
#define GSZ    (4*HID)     // 128 gate rows per layer
#define NB     296         // total blocks (2/SM on 148 SMs)
#define NLOG   264         // logits blocks (bid 32..295)
#define RPB    191         // vocab rows per logits block: 264*191 = 50424 >= 50257

// ---------------- device scratch ----------------
__device__ __align__(16) float g_h1T[HID*BD];            // [k][b]
__device__ unsigned long long g_partT[BD*NLOG];          // [batch][logits block]
__device__ unsigned g_lseqW[NLOG/4];                     // 264 byte flags (66 words)
__device__ unsigned g_hseqW[8];                          // 32 byte flags (1 sector)
__device__ unsigned g_arriveB, g_relB;                   // init barrier

// ---------------- helpers ----------------
__device__ __forceinline__ float sigf(float x){ return 1.f/(1.f+expf(-x)); }

__device__ __forceinline__ unsigned long long pk2(float lo, float hi){
    unsigned long long r;
    asm("mov.b64 %0, {%1, %2};" : "=l"(r) : "f"(lo), "f"(hi));
    return r;
}
__device__ __forceinline__ unsigned long long ffma2(unsigned long long a,
                                                    unsigned long long b,
                                                    unsigned long long c){
    unsigned long long d;
    asm("fma.rn.f32x2 %0, %1, %2, %3;" : "=l"(d) : "l"(a), "l"(b), "l"(c));
    return d;
}
__device__ __forceinline__ unsigned ordb(unsigned u){
    return (u & 0x80000000u) ? ~u : (u | 0x80000000u);
}
__device__ __forceinline__ void ldvol4(const unsigned* p, unsigned& a, unsigned& b,
                                       unsigned& c, unsigned& d){
    asm volatile("ld.volatile.global.v4.u32 {%0,%1,%2,%3}, [%4];"
                 : "=r"(a), "=r"(b), "=r"(c), "=r"(d) : "l"(p));
}

// ================= the one persistent kernel =================
__global__ void __launch_bounds__(256, 2) mega_kernel(
    const int* __restrict__ x_src, const int* __restrict__ x_tgt,
    const float* __restrict__ enc_emb,
    const float* __restrict__ eWih0, const float* __restrict__ eWhh0,
    const float* __restrict__ ebih0, const float* __restrict__ ebhh0,
    const float* __restrict__ eWih1, const float* __restrict__ eWhh1,
    const float* __restrict__ ebih1, const float* __restrict__ ebhh1,
    const float* __restrict__ dec_emb,
    const float* __restrict__ dWih0, const float* __restrict__ dWhh0,
    const float* __restrict__ dbih0, const float* __restrict__ dbhh0,
    const float* __restrict__ dWih1, const float* __restrict__ dWhh1,
    const float* __restrict__ dbih1, const float* __restrict__ dbhh1,
    const float* __restrict__ fcW,   const float* __restrict__ fcb,
    float* __restrict__ out)
{
    const int bid = blockIdx.x, tid = threadIdx.x;
    __shared__ float xs[EMB], h0s[HID], c0s[HID], h1s[HID], c1s[HID];
    __shared__ float gs[2*GSZ];
    __shared__ __align__(16) unsigned long long hp[HID*16];
    __shared__ unsigned long long cand[192];
    __shared__ int toks;

    // base snapshots (monotonic mod-256 byte flags; all blocks snapshot before
    // the init barrier, nobody advances flags until everyone passed it)
    const unsigned baseHB = (unsigned)(*(volatile unsigned char*)g_hseqW);
    const unsigned baseLB = (unsigned)(*(volatile unsigned char*)g_lseqW);
    const unsigned baseB  = *(volatile unsigned*)&g_relB;

    // ---- initial full grid barrier (replay-safe) ----
    __syncthreads();
    if (tid == 0){
        __threadfence();
        if (atomicAdd(&g_arriveB, 1u) == NB-1u){
            atomicExch(&g_arriveB, 0u);
            __threadfence();
            atomicExch(&g_relB, baseB + 1u);
        } else {
            while ((int)(*(volatile unsigned*)&g_relB - (baseB + 1u)) < 0) {}
        }
    }
    __syncthreads();

    // =====================================================================
    //                           CELL BLOCKS
    // =====================================================================
    if (bid < BD){
        // ---- encoder ----
        float wi[HID], wh[HID], bias2;
        if (tid < GSZ){
            #pragma unroll
            for (int k=0;k<HID;k++){ wi[k]=eWih0[tid*EMB+k]; wh[k]=eWhh0[tid*HID+k]; }
            bias2 = ebih0[tid] + ebhh0[tid];
        } else {
            const int j = tid - GSZ;
            #pragma unroll
            for (int k=0;k<HID;k++){ wi[k]=eWih1[j*HID+k]; wh[k]=eWhh1[j*HID+k]; }
            bias2 = ebih1[j] + ebhh1[j];
        }
        if (tid < HID){ h0s[tid]=0.f; c0s[tid]=0.f; h1s[tid]=0.f; c1s[tid]=0.f; }
        __syncthreads();

        for (int s=0;s<S_SRC;s++){
            if (tid < EMB) xs[tid] = enc_emb[(size_t)x_src[s*BD+bid]*EMB + tid];
            __syncthreads();
            if (tid < GSZ){
                float a0=bias2, a1=0.f, a2=0.f, a3=0.f;
                #pragma unroll
                for (int k=0;k<HID;k+=4){
                    a0=fmaf(xs[k],wi[k],a0);     a1=fmaf(xs[k+1],wi[k+1],a1);
                    a2=fmaf(xs[k+2],wi[k+2],a2); a3=fmaf(xs[k+3],wi[k+3],a3);
                }
                #pragma unroll
                for (int k=0;k<HID;k+=4){
                    a0=fmaf(h0s[k],wh[k],a0);     a1=fmaf(h0s[k+1],wh[k+1],a1);
                    a2=fmaf(h0s[k+2],wh[k+2],a2); a3=fmaf(h0s[k+3],wh[k+3],a3);
                }
                gs[tid] = (a0+a1)+(a2+a3);
            }
            __syncthreads();
            if (tid < HID){
                float ig=sigf(gs[tid]),        fg=sigf(gs[HID+tid]);
                float gg=tanhf(gs[2*HID+tid]), og=sigf(gs[3*HID+tid]);
                float c2 = fg*c0s[tid] + ig*gg;
                c0s[tid]=c2; h0s[tid]=og*tanhf(c2);
            }
            __syncthreads();
            if (tid >= GSZ){
                float a0=bias2, a1=0.f, a2=0.f, a3=0.f;
                #pragma unroll
                for (int k=0;k<HID;k+=4){
                    a0=fmaf(h0s[k],wi[k],a0);     a1=fmaf(h0s[k+1],wi[k+1],a1);
                    a2=fmaf(h0s[k+2],wi[k+2],a2); a3=fmaf(h0s[k+3],wi[k+3],a3);
                }
                #pragma unroll
                for (int k=0;k<HID;k+=4){
                    a0=fmaf(h1s[k],wh[k],a0);     a1=fmaf(h1s[k+1],wh[k+1],a1);
                    a2=fmaf(h1s[k+2],wh[k+2],a2); a3=fmaf(h1s[k+3],wh[k+3],a3);
                }
                gs[GSZ + (tid-GSZ)] = (a0+a1)+(a2+a3);
            }
            __syncthreads();
            if (tid < HID){
                float ig=sigf(gs[GSZ+tid]),        fg=sigf(gs[GSZ+HID+tid]);
                float gg=tanhf(gs[GSZ+2*HID+tid]), og=sigf(gs[GSZ+3*HID+tid]);
                float c2 = fg*c1s[tid] + ig*gg;
                c1s[tid]=c2; h1s[tid]=og*tanhf(c2);
            }
            __syncthreads();
        }

        // cached decoder bias + Whh·h precompute for cell(0)
        float hpart, cbias;
        if (tid < GSZ){
            cbias = dbih0[tid]+dbhh0[tid];
            float a0=0.f,a1=0.f,a2=0.f,a3=0.f;
            const float4* wh4 = (const float4*)(dWhh0 + tid*HID);
            #pragma unroll
            for (int q=0;q<8;q++){
                float4 ww = wh4[q];
                a0=fmaf(h0s[4*q],ww.x,a0);   a1=fmaf(h0s[4*q+1],ww.y,a1);
                a2=fmaf(h0s[4*q+2],ww.z,a2); a3=fmaf(h0s[4*q+3],ww.w,a3);
            }
            hpart = (a0+a1)+(a2+a3);
        } else {
            cbias = dbih1[tid-GSZ]+dbhh1[tid-GSZ];
            float a0=0.f,a1=0.f,a2=0.f,a3=0.f;
            const float4* wh4 = (const float4*)(dWhh1 + (tid-GSZ)*HID);
            #pragma unroll
            for (int q=0;q<8;q++){
                float4 ww = wh4[q];
                a0=fmaf(h1s[4*q],ww.x,a0);   a1=fmaf(h1s[4*q+1],ww.y,a1);
                a2=fmaf(h1s[4*q+2],ww.z,a2); a3=fmaf(h1s[4*q+3],ww.w,a3);
            }
            hpart = (a0+a1)+(a2+a3);
        }

        for (int t=0;t<NSTEP;t++){
            // ---- acquire token ----
            if (t == 0){
                if (tid == 0) toks = x_tgt[bid];
                __syncthreads();
            } else {
                // poll 264 byte flags (66 words) with one warp
                if (tid < 32){
                    const unsigned tb = (baseLB + (unsigned)t) & 0xFFu;
                    const unsigned tgt4 = tb * 0x01010101u;
                    volatile unsigned* lw = (volatile unsigned*)g_lseqW;
                    for(;;){
                        unsigned d = __vsub4(lw[tid], tgt4) | __vsub4(lw[tid+32], tgt4);
                        if (tid < 2) d |= __vsub4(lw[tid+64], tgt4);
                        if (__all_sync(0xFFFFFFFFu, (d & 0x80808080u) == 0u)) break;
                        __nanosleep(60);
                    }
                    __threadfence();
                }
                __syncthreads();
                // coalesced scan of this batch's 264 winner keys
                const unsigned long long* row = g_partT + (size_t)bid*NLOG;
                unsigned long long m = __ldcg(row + tid);
                if (tid < NLOG-256){
                    unsigned long long k2 = __ldcg(row + 256 + tid);
                    if (k2 > m) m = k2;
                }
                #pragma unroll
                for (int off=16; off; off>>=1){
                    unsigned long long o2 = __shfl_down_sync(0xFFFFFFFFu, m, off);
                    if (o2 > m) m = o2;
                }
                if ((tid & 31) == 0) cand[tid>>5] = m;
                __syncthreads();
                if (tid == 0){
                    unsigned long long mm = cand[0];
                    #pragma unroll
                    for (int i=1;i<8;i++) if (cand[i] > mm) mm = cand[i];
                    toks = (int)(0xFFFFFFFFu - (unsigned)(mm & 0xFFFFFFFFull));
                }
                __syncthreads();
            }
            if (tid < EMB) xs[tid] = dec_emb[(size_t)toks*EMB + tid];
            __syncthreads();

            // ---- layer 0 ----
            if (tid < GSZ){
                float a0 = cbias+hpart, a1=0.f, a2=0.f, a3=0.f;
                const float4* wi4 = (const float4*)(dWih0 + tid*EMB);
                #pragma unroll
                for (int q=0;q<8;q++){
                    float4 ww = wi4[q];
                    a0=fmaf(xs[4*q],ww.x,a0);   a1=fmaf(xs[4*q+1],ww.y,a1);
                    a2=fmaf(xs[4*q+2],ww.z,a2); a3=fmaf(xs[4*q+3],ww.w,a3);
                }
                gs[tid] = (a0+a1)+(a2+a3);
            }
            __syncthreads();
            if (tid < HID){
                float ig=sigf(gs[tid]),        fg=sigf(gs[HID+tid]);
                float gg=tanhf(gs[2*HID+tid]), og=sigf(gs[3*HID+tid]);
                float c2 = fg*c0s[tid] + ig*gg;
                c0s[tid]=c2; h0s[tid]=og*tanhf(c2);
            }
            __syncthreads();
            // ---- layer 1 ----
            if (tid >= GSZ){
                const int jj = tid - GSZ;
                float a0 = cbias+hpart, a1=0.f, a2=0.f, a3=0.f;
                const float4* wi4 = (const float4*)(dWih1 + jj*HID);
                #pragma unroll
                for (int q=0;q<8;q++){
                    float4 ww = wi4[q];
                    a0=fmaf(h0s[4*q],ww.x,a0);   a1=fmaf(h0s[4*q+1],ww.y,a1);
                    a2=fmaf(h0s[4*q+2],ww.z,a2); a3=fmaf(h0s[4*q+3],ww.w,a3);
                }
                gs[GSZ+jj] = (a0+a1)+(a2+a3);
            }
            __syncthreads();
            if (tid < HID){
                float ig=sigf(gs[GSZ+tid]),        fg=sigf(gs[GSZ+HID+tid]);
                float gg=tanhf(gs[GSZ+2*HID+tid]), og=sigf(gs[GSZ+3*HID+tid]);
                float c2 = fg*c1s[tid] + ig*gg;
                float h2 = og*tanhf(c2);
                c1s[tid]=c2; h1s[tid]=h2;
                g_h1T[tid*BD + bid] = h2;
            }
            __syncthreads();
            if (tid == 0){
                __threadfence();
                ((volatile unsigned char*)g_hseqW)[bid] =
                    (unsigned char)(baseHB + (unsigned)t + 1u);
            }
            // precompute Whh·h for next cell (overlapped with logits phase)
            if (t < NSTEP-1){
                if (tid < GSZ){
                    float a0=0.f,a1=0.f,a2=0.f,a3=0.f;
                    const float4* wh4 = (const float4*)(dWhh0 + tid*HID);
                    #pragma unroll
                    for (int q=0;q<8;q++){
                        float4 ww = wh4[q];
                        a0=fmaf(h0s[4*q],ww.x,a0);   a1=fmaf(h0s[4*q+1],ww.y,a1);
                        a2=fmaf(h0s[4*q+2],ww.z,a2); a3=fmaf(h0s[4*q+3],ww.w,a3);
                    }
                    hpart = (a0+a1)+(a2+a3);
                } else {
                    float a0=0.f,a1=0.f,a2=0.f,a3=0.f;
                    const float4* wh4 = (const float4*)(dWhh1 + (tid-GSZ)*HID);
                    #pragma unroll
                    for (int q=0;q<8;q++){
                        float4 ww = wh4[q];
                        a0=fmaf(h1s[4*q],ww.x,a0);   a1=fmaf(h1s[4*q+1],ww.y,a1);
                        a2=fmaf(h1s[4*q+2],ww.z,a2); a3=fmaf(h1s[4*q+3],ww.w,a3);
                    }
                    hpart = (a0+a1)+(a2+a3);
                }
            }
        }
        return;
    }

    // =====================================================================
    //                          LOGITS BLOCKS
    // =====================================================================
    const int L    = bid - BD;                         // 0..263
    const int sel  = (bid >= 180) ? 1 : 0;             // SMSP balance vs partner block
    const int w8   = tid >> 5, lane = tid & 31;
    const bool wact = sel ? ((w8 < 4) || (w8 >= 6)) : (w8 < 6);
    const int wslot = sel ? ((w8 < 4) ? w8 : (w8 - 2)) : w8;
    const int j    = wslot*32 + lane;                  // 0..191
    const int v    = L*RPB + j;
    const bool valid = wact && (j < RPB) && (v < VOCABN);
    const int vc   = valid ? v : (VOCABN-1);

    float w[HID];
    {
        const float4* w4 = (const float4*)(fcW + (size_t)vc*HID);
        #pragma unroll
        for (int q=0;q<8;q++){
            float4 t4 = w4[q];
            w[4*q]=t4.x; w[4*q+1]=t4.y; w[4*q+2]=t4.z; w[4*q+3]=t4.w;
        }
    }
    const float bias = fcb[vc];

    for (int t=0;t<NSTEP;t++){
        // ---- wait for all 32 h1 columns (single-sector byte flags, 1 poller) ----
        if (tid == 0){
            const unsigned tb = (baseHB + (unsigned)t + 1u) & 0xFFu;
            const unsigned tgt4 = tb * 0x01010101u;
            for(;;){
                unsigned a0,a1,a2,a3,b0,b1,b2,b3;
                ldvol4(g_hseqW, a0,a1,a2,a3);
                ldvol4(g_hseqW+4, b0,b1,b2,b3);
                unsigned d = __vsub4(a0,tgt4) | __vsub4(a1,tgt4) |
                             __vsub4(a2,tgt4) | __vsub4(a3,tgt4) |
                             __vsub4(b0,tgt4) | __vsub4(b1,tgt4) |
                             __vsub4(b2,tgt4) | __vsub4(b3,tgt4);
                if ((d & 0x80808080u) == 0u) break;
                __nanosleep(t == 0 ? 1024u : 60u);
            }
            __threadfence();
        }
        __syncthreads();

        // ---- load h, zero candidates ----
        {
            const unsigned long long* src = (const unsigned long long*)g_h1T;
            hp[tid]       = __ldcg(src + tid);
            hp[tid + 256] = __ldcg(src + tid + 256);
        }
        if (tid < 192) cand[tid] = 0ull;
        __syncthreads();

        // ---- FFMA2 logits ----
        unsigned long long acc[16];
        if (wact){
            {
                unsigned long long bb = pk2(bias, bias);
                #pragma unroll
                for (int p=0;p<16;p++) acc[p]=bb;
            }
            #pragma unroll
            for (int k=0;k<HID;k++){
                unsigned long long ww = pk2(w[k], w[k]);
                const ulonglong2* hr = (const ulonglong2*)(hp + k*16);
                #pragma unroll
                for (int q=0;q<8;q++){
                    ulonglong2 h2 = hr[q];
                    acc[2*q]   = ffma2(h2.x, ww, acc[2*q]);
                    acc[2*q+1] = ffma2(h2.y, ww, acc[2*q+1]);
                }
            }
        }

        if (t < NSTEP-1){
            // ---- per-warp argmax, publish winners BEFORE out stores ----
            if (wact){
                const unsigned vk = 0xFFFFFFFFu - (unsigned)v;
                #pragma unroll
                for (int b=0;b<BD;b++){
                    unsigned long long a = acc[b>>1];
                    unsigned u = (b&1) ? (unsigned)(a>>32) : (unsigned)(a & 0xFFFFFFFFull);
                    unsigned o_ = valid ? ordb(u) : 0u;
                    unsigned mx = __reduce_max_sync(0xFFFFFFFFu, o_);
                    unsigned ball = __ballot_sync(0xFFFFFFFFu, (o_ == mx) && valid);
                    if (ball){
                        int leader = __ffs(ball) - 1;
                        if (lane == leader)
                            cand[wslot*BD + b] = ((unsigned long long)mx << 32) | (unsigned long long)vk;
                    }
                }
            }
            __syncthreads();
            if (tid < BD){
                unsigned long long m = cand[tid];
                #pragma unroll
                for (int wq=1;wq<6;wq++){
                    unsigned long long k = cand[wq*BD + tid];
                    if (k > m) m = k;
                }
                g_partT[(size_t)tid*NLOG + L] = m;     // [batch][block], plain store
            }
            __syncthreads();
            if (tid == 0){
                __threadfence();
                ((volatile unsigned char*)g_lseqW)[L] =
                    (unsigned char)(baseLB + (unsigned)t + 1u);
            }
        }

        // ---- output stores (off critical path) ----
        if (valid){
            float* o = out + ((size_t)t*BD)*VOCABN + v;
            #pragma unroll
            for (int p=0;p<16;p++){
                unsigned long long a = acc[p];
                o[(size_t)(2*p)*VOCABN]   = __uint_as_float((unsigned)(a & 0xFFFFFFFFull));
                o[(size_t)(2*p+1)*VOCABN] = __uint_as_float((unsigned)(a >> 32));
            }
        }
    }
}

// ================= launch =================
extern "C" void kernel_launch(void* const* d_in, const int* in_sizes, int n_in,
                              void* d_out, int out_size)
{
    const int*   x_src  = (const int*)  d_in[0];
    const int*   x_tgt  = (const int*)  d_in[1];
    const float* enc_emb= (const float*)d_in[2];
    const float* eWih0  = (const float*)d_in[3];
    const float* eWhh0  = (const float*)d_in[4];
    const float* ebih0  = (const float*)d_in[5];
    const float* ebhh0  = (const float*)d_in[6];
    const float* eWih1  = (const float*)d_in[7];
    const float* eWhh1  = (const float*)d_in[8];
    const float* ebih1  = (const float*)d_in[9];
    const float* ebhh1  = (const float*)d_in[10];
    const float* dec_emb= (const float*)d_in[11];
    const float* dWih0  = (const float*)d_in[12];
    const float* dWhh0  = (const float*)d_in[13];
    const float* dbih0  = (const float*)d_in[14];
    const float* dbhh0  = (const float*)d_in[15];
    const float* dWih1  = (const float*)d_in[16];
    const float* dWhh1  = (const float*)d_in[17];
    const float* dbih1  = (const float*)d_in[18];
    const float* dbhh1  = (const float*)d_in[19];
    const float* fcW    = (const float*)d_in[20];
    const float* fcb    = (const float*)d_in[21];
    float* out = (float*)d_out;

    mega_kernel<<<NB, 256>>>(x_src, x_tgt, enc_emb,
                             eWih0,eWhh0,ebih0,ebhh0,eWih1,eWhh1,ebih1,ebhh1,
                             dec_emb,
                             dWih0,dWhh0,dbih0,dbhh0,dWih1,dWhh1,dbih1,dbhh1,
                             fcW, fcb, out);
}

// round 16
// speedup vs baseline: 1.9195x; 1.9195x over previous
#include <cuda_runtime.h>

#define HID    32
#define EMB    32
#define BD     32
#define VOCABN 50257
#define S_SRC  64
#define NSTEP  63
#define GSZ    (4*HID)     // 128 gate rows per layer
#define NB     296         // 2 blocks per SM
#define RPB    170         // vocab rows per block: 296*170 = 50320 >= 50257

// ---------------- device scratch ----------------
__device__ __align__(16) float g_h1T[HID*BD];          // [k][b]
__device__ unsigned long long g_partT[BD*NB];          // [batch][block] winner keys (seq-embedded)
__device__ unsigned g_hflag[BD*32];                    // per-batch h flags, 128B apart
__device__ unsigned g_baseS;                           // replay base (monotonic)
__device__ unsigned g_arriveB, g_relB;                 // init barrier

// ---------------- helpers ----------------
__device__ __forceinline__ float sigf(float x){ return 1.f/(1.f+expf(-x)); }

__device__ __forceinline__ unsigned long long pk2(float lo, float hi){
    unsigned long long r;
    asm("mov.b64 %0, {%1, %2};" : "=l"(r) : "f"(lo), "f"(hi));
    return r;
}
__device__ __forceinline__ unsigned long long ffma2(unsigned long long a,
                                                    unsigned long long b,
                                                    unsigned long long c){
    unsigned long long d;
    asm("fma.rn.f32x2 %0, %1, %2, %3;" : "=l"(d) : "l"(a), "l"(b), "l"(c));
    return d;
}
__device__ __forceinline__ unsigned ordb(unsigned u){
    return (u & 0x80000000u) ? ~u : (u | 0x80000000u);
}
__device__ __forceinline__ unsigned long long ldcg64(const unsigned long long* p){
    unsigned long long v;
    asm volatile("ld.global.cg.u64 %0, [%1];" : "=l"(v) : "l"(p));
    return v;
}
__device__ __forceinline__ void strel32(unsigned* p, unsigned v){
    asm volatile("st.release.gpu.global.u32 [%0], %1;" :: "l"(p), "r"(v) : "memory");
}
__device__ __forceinline__ unsigned ldacq32(const unsigned* p){
    unsigned v;
    asm volatile("ld.acquire.gpu.global.u32 %0, [%1];" : "=r"(v) : "l"(p) : "memory");
    return v;
}

// ================= the one persistent kernel =================
__global__ void __launch_bounds__(256, 2) mega_kernel(
    const int* __restrict__ x_src, const int* __restrict__ x_tgt,
    const float* __restrict__ enc_emb,
    const float* __restrict__ eWih0, const float* __restrict__ eWhh0,
    const float* __restrict__ ebih0, const float* __restrict__ ebhh0,
    const float* __restrict__ eWih1, const float* __restrict__ eWhh1,
    const float* __restrict__ ebih1, const float* __restrict__ ebhh1,
    const float* __restrict__ dec_emb,
    const float* __restrict__ dWih0, const float* __restrict__ dWhh0,
    const float* __restrict__ dbih0, const float* __restrict__ dbhh0,
    const float* __restrict__ dWih1, const float* __restrict__ dWhh1,
    const float* __restrict__ dbih1, const float* __restrict__ dbhh1,
    const float* __restrict__ fcW,   const float* __restrict__ fcb,
    float* __restrict__ out)
{
    const int bid = blockIdx.x, tid = threadIdx.x;
    __shared__ float xs[EMB], h0s[HID], c0s[HID], h1s[HID], c1s[HID];
    __shared__ float gs[2*GSZ];
    __shared__ __align__(16) unsigned long long hp[HID*16];
    __shared__ unsigned long long cand[256];
    __shared__ int toks;

    // replay base snapshot: read by ALL blocks before the init barrier;
    // advanced by block 0 only after everyone passed the barrier.
    const unsigned baseS = *(volatile unsigned*)&g_baseS;
    const unsigned baseB = *(volatile unsigned*)&g_relB;

    // ---- initial full grid barrier (replay-safe) ----
    __syncthreads();
    if (tid == 0){
        __threadfence();
        if (atomicAdd(&g_arriveB, 1u) == NB-1u){
            atomicExch(&g_arriveB, 0u);
            __threadfence();
            atomicExch(&g_relB, baseB + 1u);
        } else {
            while ((int)(*(volatile unsigned*)&g_relB - (baseB + 1u)) < 0) {}
        }
    }
    __syncthreads();
    if (bid == 0 && tid == 0) *(volatile unsigned*)&g_baseS = baseS + (unsigned)NSTEP;

    float hpart = 0.f;   // precomputed Whh·h contribution for the next cell
    float cbias = 0.f;   // cached gate bias (cell blocks)

    // ================= encoder (blocks 0..31, one batch each) =================
    if (bid < BD){
        float wi[HID], wh[HID], bias2;
        if (tid < GSZ){
            #pragma unroll
            for (int k=0;k<HID;k++){ wi[k]=eWih0[tid*EMB+k]; wh[k]=eWhh0[tid*HID+k]; }
            bias2 = ebih0[tid] + ebhh0[tid];
        } else {
            const int j = tid - GSZ;
            #pragma unroll
            for (int k=0;k<HID;k++){ wi[k]=eWih1[j*HID+k]; wh[k]=eWhh1[j*HID+k]; }
            bias2 = ebih1[j] + ebhh1[j];
        }
        if (tid < HID){ h0s[tid]=0.f; c0s[tid]=0.f; h1s[tid]=0.f; c1s[tid]=0.f; }
        __syncthreads();

        for (int s=0;s<S_SRC;s++){
            if (tid < EMB) xs[tid] = enc_emb[(size_t)x_src[s*BD+bid]*EMB + tid];
            __syncthreads();
            if (tid < GSZ){
                float a0=bias2, a1=0.f, a2=0.f, a3=0.f;
                #pragma unroll
                for (int k=0;k<HID;k+=4){
                    a0=fmaf(xs[k],wi[k],a0);     a1=fmaf(xs[k+1],wi[k+1],a1);
                    a2=fmaf(xs[k+2],wi[k+2],a2); a3=fmaf(xs[k+3],wi[k+3],a3);
                }
                #pragma unroll
                for (int k=0;k<HID;k+=4){
                    a0=fmaf(h0s[k],wh[k],a0);     a1=fmaf(h0s[k+1],wh[k+1],a1);
                    a2=fmaf(h0s[k+2],wh[k+2],a2); a3=fmaf(h0s[k+3],wh[k+3],a3);
                }
                gs[tid] = (a0+a1)+(a2+a3);
            }
            __syncthreads();
            if (tid < HID){
                float ig=sigf(gs[tid]),        fg=sigf(gs[HID+tid]);
                float gg=tanhf(gs[2*HID+tid]), og=sigf(gs[3*HID+tid]);
                float c2 = fg*c0s[tid] + ig*gg;
                c0s[tid]=c2; h0s[tid]=og*tanhf(c2);
            }
            __syncthreads();
            if (tid >= GSZ){
                float a0=bias2, a1=0.f, a2=0.f, a3=0.f;
                #pragma unroll
                for (int k=0;k<HID;k+=4){
                    a0=fmaf(h0s[k],wi[k],a0);     a1=fmaf(h0s[k+1],wi[k+1],a1);
                    a2=fmaf(h0s[k+2],wi[k+2],a2); a3=fmaf(h0s[k+3],wi[k+3],a3);
                }
                #pragma unroll
                for (int k=0;k<HID;k+=4){
                    a0=fmaf(h1s[k],wh[k],a0);     a1=fmaf(h1s[k+1],wh[k+1],a1);
                    a2=fmaf(h1s[k+2],wh[k+2],a2); a3=fmaf(h1s[k+3],wh[k+3],a3);
                }
                gs[GSZ + (tid-GSZ)] = (a0+a1)+(a2+a3);
            }
            __syncthreads();
            if (tid < HID){
                float ig=sigf(gs[GSZ+tid]),        fg=sigf(gs[GSZ+HID+tid]);
                float gg=tanhf(gs[GSZ+2*HID+tid]), og=sigf(gs[GSZ+3*HID+tid]);
                float c2 = fg*c1s[tid] + ig*gg;
                c1s[tid]=c2; h1s[tid]=og*tanhf(c2);
            }
            __syncthreads();
        }
        // cached decoder bias + Whh·h precompute for cell(0)
        if (tid < GSZ){
            cbias = dbih0[tid]+dbhh0[tid];
            float a0=0.f,a1=0.f,a2=0.f,a3=0.f;
            const float4* wh4 = (const float4*)(dWhh0 + tid*HID);
            #pragma unroll
            for (int q=0;q<8;q++){
                float4 ww = wh4[q];
                a0=fmaf(h0s[4*q],ww.x,a0);   a1=fmaf(h0s[4*q+1],ww.y,a1);
                a2=fmaf(h0s[4*q+2],ww.z,a2); a3=fmaf(h0s[4*q+3],ww.w,a3);
            }
            hpart = (a0+a1)+(a2+a3);
        } else {
            cbias = dbih1[tid-GSZ]+dbhh1[tid-GSZ];
            float a0=0.f,a1=0.f,a2=0.f,a3=0.f;
            const float4* wh4 = (const float4*)(dWhh1 + (tid-GSZ)*HID);
            #pragma unroll
            for (int q=0;q<8;q++){
                float4 ww = wh4[q];
                a0=fmaf(h1s[4*q],ww.x,a0);   a1=fmaf(h1s[4*q+1],ww.y,a1);
                a2=fmaf(h1s[4*q+2],ww.z,a2); a3=fmaf(h1s[4*q+3],ww.w,a3);
            }
            hpart = (a0+a1)+(a2+a3);
        }
    }

    // ================= persistent fc weights, SMSP-balanced warp mapping =================
    const int sel  = (bid >= NB/2) ? 1 : 0;
    const int w8   = tid >> 5, lane = tid & 31;
    const bool wact = sel ? ((w8 < 4) || (w8 >= 6)) : (w8 < 6);
    const int wslot = sel ? ((w8 < 4) ? w8 : (w8 - 2)) : w8;
    const int j    = wslot*32 + lane;                 // 0..191
    const int v    = bid*RPB + j;
    const bool valid = wact && (j < RPB) && (v < VOCABN);
    const int vc   = valid ? v : (VOCABN-1);

    float w[HID];
    {
        const float4* w4 = (const float4*)(fcW + (size_t)vc*HID);
        #pragma unroll
        for (int q=0;q<8;q++){
            float4 t4 = w4[q];
            w[4*q]=t4.x; w[4*q+1]=t4.y; w[4*q+2]=t4.z; w[4*q+3]=t4.w;
        }
    }
    const float bias = fcb[vc];

    // ================= decoder loop =================
    for (int t=0;t<NSTEP;t++){
        const unsigned hseq = baseS + (unsigned)t + 1u;          // h(t) flag value
        const unsigned wseq = (baseS + (unsigned)t + 1u) & 0x7FFFu;  // winner(t) tag

        // ---------- cell (blocks 0..31) ----------
        if (bid < BD){
            if (t == 0){
                if (tid == 0) toks = x_tgt[bid];
                __syncthreads();
            } else {
                // poll-with-data: winner(t-1) keys carry their own seq tag
                const unsigned wtgt = (baseS + (unsigned)t) & 0x7FFFu;
                const unsigned long long* row = g_partT + (size_t)bid*NB;
                const bool two = tid < (NB-256);
                unsigned long long k0, k1 = 0ull;
                for(;;){
                    k0 = ldcg64(row + tid);
                    bool ok = ((unsigned)k0 & 0x7FFFu) == wtgt;
                    if (two){
                        k1 = ldcg64(row + 256 + tid);
                        ok &= (((unsigned)k1 & 0x7FFFu) == wtgt);
                    }
                    if (__syncthreads_and((int)ok)) break;
                    __nanosleep(40);
                }
                unsigned long long m = (k1 > k0) ? k1 : k0;
                #pragma unroll
                for (int off=16; off; off>>=1){
                    unsigned long long o2 = __shfl_down_sync(0xFFFFFFFFu, m, off);
                    if (o2 > m) m = o2;
                }
                if ((tid & 31) == 0) cand[tid>>5] = m;
                __syncthreads();
                if (tid == 0){
                    unsigned long long mm = cand[0];
                    #pragma unroll
                    for (int i=1;i<8;i++) if (cand[i] > mm) mm = cand[i];
                    toks = (int)(0x1FFFFu - ((unsigned)(mm >> 15) & 0x1FFFFu));
                }
                __syncthreads();
            }
            if (tid < EMB) xs[tid] = dec_emb[(size_t)toks*EMB + tid];
            __syncthreads();

            if (tid < GSZ){
                float a0 = cbias+hpart, a1=0.f, a2=0.f, a3=0.f;
                const float4* wi4 = (const float4*)(dWih0 + tid*EMB);
                #pragma unroll
                for (int q=0;q<8;q++){
                    float4 ww = wi4[q];
                    a0=fmaf(xs[4*q],ww.x,a0);   a1=fmaf(xs[4*q+1],ww.y,a1);
                    a2=fmaf(xs[4*q+2],ww.z,a2); a3=fmaf(xs[4*q+3],ww.w,a3);
                }
                gs[tid] = (a0+a1)+(a2+a3);
            }
            __syncthreads();
            if (tid < HID){
                float ig=sigf(gs[tid]),        fg=sigf(gs[HID+tid]);
                float gg=tanhf(gs[2*HID+tid]), og=sigf(gs[3*HID+tid]);
                float c2 = fg*c0s[tid] + ig*gg;
                c0s[tid]=c2; h0s[tid]=og*tanhf(c2);
            }
            __syncthreads();
            if (tid >= GSZ){
                const int jj = tid - GSZ;
                float a0 = cbias+hpart, a1=0.f, a2=0.f, a3=0.f;
                const float4* wi4 = (const float4*)(dWih1 + jj*HID);
                #pragma unroll
                for (int q=0;q<8;q++){
                    float4 ww = wi4[q];
                    a0=fmaf(h0s[4*q],ww.x,a0);   a1=fmaf(h0s[4*q+1],ww.y,a1);
                    a2=fmaf(h0s[4*q+2],ww.z,a2); a3=fmaf(h0s[4*q+3],ww.w,a3);
                }
                gs[GSZ+jj] = (a0+a1)+(a2+a3);
            }
            __syncthreads();
            if (tid < HID){
                float ig=sigf(gs[GSZ+tid]),        fg=sigf(gs[GSZ+HID+tid]);
                float gg=tanhf(gs[GSZ+2*HID+tid]), og=sigf(gs[GSZ+3*HID+tid]);
                float c2 = fg*c1s[tid] + ig*gg;
                float h2 = og*tanhf(c2);
                c1s[tid]=c2; h1s[tid]=h2;
                g_h1T[tid*BD + bid] = h2;
            }
            __syncthreads();
            if (tid == 0) strel32(&g_hflag[bid*32], hseq);   // release: orders h stores
            // precompute Whh·h for next cell (hidden behind logits phase)
            if (t < NSTEP-1){
                if (tid < GSZ){
                    float a0=0.f,a1=0.f,a2=0.f,a3=0.f;
                    const float4* wh4 = (const float4*)(dWhh0 + tid*HID);
                    #pragma unroll
                    for (int q=0;q<8;q++){
                        float4 ww = wh4[q];
                        a0=fmaf(h0s[4*q],ww.x,a0);   a1=fmaf(h0s[4*q+1],ww.y,a1);
                        a2=fmaf(h0s[4*q+2],ww.z,a2); a3=fmaf(h0s[4*q+3],ww.w,a3);
                    }
                    hpart = (a0+a1)+(a2+a3);
                } else {
                    float a0=0.f,a1=0.f,a2=0.f,a3=0.f;
                    const float4* wh4 = (const float4*)(dWhh1 + (tid-GSZ)*HID);
                    #pragma unroll
                    for (int q=0;q<8;q++){
                        float4 ww = wh4[q];
                        a0=fmaf(h1s[4*q],ww.x,a0);   a1=fmaf(h1s[4*q+1],ww.y,a1);
                        a2=fmaf(h1s[4*q+2],ww.z,a2); a3=fmaf(h1s[4*q+3],ww.w,a3);
                    }
                    hpart = (a0+a1)+(a2+a3);
                }
            }
        }

        // ---------- wait: all 32 h1 columns ready (1 warp, acquire loads) ----------
        if (tid < 32){
            const unsigned* fp = &g_hflag[tid*32];
            for(;;){
                unsigned f = ldacq32(fp);
                if (__all_sync(0xFFFFFFFFu, (int)(f - hseq) >= 0)) break;
                __nanosleep(40);
            }
        }
        __syncthreads();

        // ---------- logits (all blocks) ----------
        {
            const unsigned long long* src = (const unsigned long long*)g_h1T;
            hp[tid]       = ldcg64(src + tid);
            hp[tid + 256] = ldcg64(src + tid + 256);
        }
        cand[tid] = 0ull;
        __syncthreads();

        unsigned long long acc[16];
        if (wact){
            {
                unsigned long long bb = pk2(bias, bias);
                #pragma unroll
                for (int p=0;p<16;p++) acc[p]=bb;
            }
            #pragma unroll
            for (int k=0;k<HID;k++){
                unsigned long long ww = pk2(w[k], w[k]);
                const ulonglong2* hr = (const ulonglong2*)(hp + k*16);
                #pragma unroll
                for (int q=0;q<8;q++){
                    ulonglong2 h2 = hr[q];
                    acc[2*q]   = ffma2(h2.x, ww, acc[2*q]);
                    acc[2*q+1] = ffma2(h2.y, ww, acc[2*q+1]);
                }
            }
        }

        if (t < NSTEP-1){
            // per-warp argmax; winner keys published with embedded seq, no fence
            if (wact){
                const unsigned long long vk = ((unsigned long long)(0x1FFFFu - (unsigned)v)) << 15;
                #pragma unroll
                for (int b=0;b<BD;b++){
                    unsigned long long a = acc[b>>1];
                    unsigned u = (b&1) ? (unsigned)(a>>32) : (unsigned)(a & 0xFFFFFFFFull);
                    unsigned o_ = valid ? ordb(u) : 0u;
                    unsigned mx = __reduce_max_sync(0xFFFFFFFFu, o_);
                    unsigned ball = __ballot_sync(0xFFFFFFFFu, (o_ == mx) && valid);
                    if (ball){
                        int leader = __ffs(ball) - 1;
                        if (lane == leader)
                            cand[wslot*BD + b] = ((unsigned long long)mx << 32) | vk;
                    }
                }
            }
            __syncthreads();
            if (tid < BD){
                unsigned long long m = cand[tid];
                #pragma unroll
                for (int wq=1;wq<6;wq++){
                    unsigned long long k = cand[wq*BD + tid];
                    if (k > m) m = k;
                }
                // self-validating key: data + seq in one aligned u64 store
                *(volatile unsigned long long*)&g_partT[(size_t)tid*NB + bid] =
                    m | (unsigned long long)wseq;
            }
        }

        // output stores — off the critical path
        if (valid){
            float* o = out + ((size_t)t*BD)*VOCABN + v;
            #pragma unroll
            for (int p=0;p<16;p++){
                unsigned long long a = acc[p];
                o[(size_t)(2*p)*VOCABN]   = __uint_as_float((unsigned)(a & 0xFFFFFFFFull));
                o[(size_t)(2*p+1)*VOCABN] = __uint_as_float((unsigned)(a >> 32));
            }
        }
    }
}

// ================= launch =================
extern "C" void kernel_launch(void* const* d_in, const int* in_sizes, int n_in,
                              void* d_out, int out_size)
{
    const int*   x_src  = (const int*)  d_in[0];
    const int*   x_tgt  = (const int*)  d_in[1];
    const float* enc_emb= (const float*)d_in[2];
    const float* eWih0  = (const float*)d_in[3];
    const float* eWhh0  = (const float*)d_in[4];
    const float* ebih0  = (const float*)d_in[5];
    const float* ebhh0  = (const float*)d_in[6];
    const float* eWih1  = (const float*)d_in[7];
    const float* eWhh1  = (const float*)d_in[8];
    const float* ebih1  = (const float*)d_in[9];
    const float* ebhh1  = (const float*)d_in[10];
    const float* dec_emb= (const float*)d_in[11];
    const float* dWih0  = (const float*)d_in[12];
    const float* dWhh0  = (const float*)d_in[13];
    const float* dbih0  = (const float*)d_in[14];
    const float* dbhh0  = (const float*)d_in[15];
    const float* dWih1  = (const float*)d_in[16];
    const float* dWhh1  = (const float*)d_in[17];
    const float* dbih1  = (const float*)d_in[18];
    const float* dbhh1  = (const float*)d_in[19];
    const float* fcW    = (const float*)d_in[20];
    const float* fcb    = (const float*)d_in[21];
    float* out = (float*)d_out;

    mega_kernel<<<NB, 256>>>(x_src, x_tgt, enc_emb,
                             eWih0,eWhh0,ebih0,ebhh0,eWih1,eWhh1,ebih1,ebhh1,
                             dec_emb,
                             dWih0,dWhh0,dbih0,dbhh0,dWih1,dWhh1,dbih1,dbhh1,
                             fcW, fcb, out);
}